// round 8
// baseline (speedup 1.0000x reference)
#include <cuda_runtime.h>
#include <math.h>

#define HH 64
#define WW 64
#define BB 2
#define CC 128
#define NH 4
#define DH 32
#define KS 7
#define KK 49
#define NTOK (BB*HH*WW)   // 8192
#define QKV_STRIDE (3*CC) // 384

// scratch (device globals: no allocation allowed)
__device__ float g_qkv[NTOK * 3 * CC];
__device__ float g_att[NTOK * CC];
__device__ float g_y1 [NTOK * CC];
__device__ float g_y2 [NTOK * CC];

// ----------------------------------------------------------------------------
// tf32 helpers
// ----------------------------------------------------------------------------
__device__ __forceinline__ unsigned f2tf32(float f) {
    unsigned u;
    asm("cvt.rna.tf32.f32 %0, %1;" : "=r"(u) : "f"(f));
    return u;
}
__device__ __forceinline__ void split_tf32(float f, unsigned& hi, unsigned& lo) {
    hi = f2tf32(f);
    lo = f2tf32(f - __uint_as_float(hi));
}
__device__ __forceinline__ void mma8(float* c, const unsigned* a, const unsigned* b) {
    asm volatile(
        "mma.sync.aligned.m16n8k8.row.col.f32.tf32.tf32.f32 "
        "{%0,%1,%2,%3}, {%4,%5,%6,%7}, {%8,%9}, {%0,%1,%2,%3};"
        : "+f"(c[0]), "+f"(c[1]), "+f"(c[2]), "+f"(c[3])
        : "r"(a[0]), "r"(a[1]), "r"(a[2]), "r"(a[3]),
          "r"(b[0]), "r"(b[1]));
}

// ----------------------------------------------------------------------------
// Tensor-core SGEMM v2 (3xTF32, split at staging): C = A @ W^T + bias.
// BM=BN=64, BK=64 (2 k-tiles). 256 thr = 8 warps (2m x 4n), warp tile 32x16.
// Four smem planes of pre-split tf32: A-hi/A-lo/B-hi/B-lo, [row][k] pitch 68.
// Fragment loads are conflict-free (banks 4g + t4, all distinct).
// ----------------------------------------------------------------------------
#define SPK 68
#define GEMM_SMEM (4*64*SPK*4)   // 69632 bytes

__global__ void __launch_bounds__(256) sgemm_tc2_kernel(
    const float* __restrict__ A, int a_nchw,
    const float* __restrict__ W,
    const float* __restrict__ bias,
    float* __restrict__ Cout, int N)
{
    extern __shared__ unsigned usm[];
    unsigned* Ah = usm;
    unsigned* Al = Ah + 64*SPK;
    unsigned* Bh = Al + 64*SPK;
    unsigned* Bl = Bh + 64*SPK;

    const int bm = blockIdx.x * 64;
    const int bn = blockIdx.y * 64;
    const int tid  = threadIdx.x;
    const int w    = tid >> 5;
    const int lane = tid & 31;
    const int wm = w >> 2;          // 0..1
    const int wn = w & 3;           // 0..3
    const int g  = lane >> 2;       // 0..7
    const int t4 = lane & 3;        // 0..3

    float acc[2][2][4];
    #pragma unroll
    for (int mi = 0; mi < 2; mi++)
        #pragma unroll
        for (int ni = 0; ni < 2; ni++)
            #pragma unroll
            for (int u = 0; u < 4; u++) acc[mi][ni][u] = 0.f;

    #pragma unroll
    for (int kt = 0; kt < 2; kt++) {
        if (kt) __syncthreads();
        // ---- stage A k-tile (64m x 64k), split hi/lo ----
        if (a_nchw) {
            const int b = bm >> 12;
            const int sp0 = bm & 4095;
            #pragma unroll
            for (int r = 0; r < 4; r++) {
                int idx = tid + r*256;          // 64k x 16m4
                int k = idx >> 4, m4 = idx & 15;
                float4 v = *(const float4*)&A[(b*CC + kt*64 + k)*4096 + sp0 + m4*4];
                unsigned h0,l0,h1,l1,h2,l2,h3,l3;
                split_tf32(v.x, h0, l0); split_tf32(v.y, h1, l1);
                split_tf32(v.z, h2, l2); split_tf32(v.w, h3, l3);
                Ah[(m4*4+0)*SPK + k] = h0; Al[(m4*4+0)*SPK + k] = l0;
                Ah[(m4*4+1)*SPK + k] = h1; Al[(m4*4+1)*SPK + k] = l1;
                Ah[(m4*4+2)*SPK + k] = h2; Al[(m4*4+2)*SPK + k] = l2;
                Ah[(m4*4+3)*SPK + k] = h3; Al[(m4*4+3)*SPK + k] = l3;
            }
        } else {
            #pragma unroll
            for (int r = 0; r < 4; r++) {
                int idx = tid + r*256;          // 64m x 16k4
                int m = idx >> 4, k4 = idx & 15;
                float4 v = ((const float4*)A)[(bm + m)*32 + kt*16 + k4];
                uint4 hv, lv;
                split_tf32(v.x, hv.x, lv.x); split_tf32(v.y, hv.y, lv.y);
                split_tf32(v.z, hv.z, lv.z); split_tf32(v.w, hv.w, lv.w);
                *(uint4*)&Ah[m*SPK + k4*4] = hv;
                *(uint4*)&Al[m*SPK + k4*4] = lv;
            }
        }
        // ---- stage W k-tile (64n x 64k), split hi/lo ----
        #pragma unroll
        for (int r = 0; r < 4; r++) {
            int idx = tid + r*256;
            int n = idx >> 4, k4 = idx & 15;
            float4 v = ((const float4*)W)[(bn + n)*32 + kt*16 + k4];
            uint4 hv, lv;
            split_tf32(v.x, hv.x, lv.x); split_tf32(v.y, hv.y, lv.y);
            split_tf32(v.z, hv.z, lv.z); split_tf32(v.w, hv.w, lv.w);
            *(uint4*)&Bh[n*SPK + k4*4] = hv;
            *(uint4*)&Bl[n*SPK + k4*4] = lv;
        }
        __syncthreads();

        // ---- 8 k-steps of m16n8k8: pure LDS + MMA ----
        #pragma unroll
        for (int ks = 0; ks < 8; ks++) {
            const int k0 = ks*8;
            unsigned ah[2][4], al[2][4];
            #pragma unroll
            for (int mi = 0; mi < 2; mi++) {
                const int r0 = (wm*32 + mi*16 + g)*SPK + k0 + t4;
                const int r8 = r0 + 8*SPK;
                ah[mi][0] = Ah[r0];     ah[mi][1] = Ah[r8];
                ah[mi][2] = Ah[r0 + 4]; ah[mi][3] = Ah[r8 + 4];
                al[mi][0] = Al[r0];     al[mi][1] = Al[r8];
                al[mi][2] = Al[r0 + 4]; al[mi][3] = Al[r8 + 4];
            }
            unsigned bh[2][2], bl[2][2];
            #pragma unroll
            for (int ni = 0; ni < 2; ni++) {
                const int r0 = (wn*16 + ni*8 + g)*SPK + k0 + t4;
                bh[ni][0] = Bh[r0]; bh[ni][1] = Bh[r0 + 4];
                bl[ni][0] = Bl[r0]; bl[ni][1] = Bl[r0 + 4];
            }
            #pragma unroll
            for (int mi = 0; mi < 2; mi++)
                #pragma unroll
                for (int ni = 0; ni < 2; ni++) {
                    mma8(acc[mi][ni], ah[mi], bh[ni]);
                    mma8(acc[mi][ni], ah[mi], bl[ni]);
                    mma8(acc[mi][ni], al[mi], bh[ni]);
                }
        }
    }

    // ---- epilogue ----
    #pragma unroll
    for (int mi = 0; mi < 2; mi++) {
        #pragma unroll
        for (int ni = 0; ni < 2; ni++) {
            const int row0 = bm + wm*32 + mi*16 + g;
            const int col  = bn + wn*16 + ni*8 + t4*2;
            float b0 = bias[col], b1 = bias[col + 1];
            float2 v0 = make_float2(acc[mi][ni][0] + b0, acc[mi][ni][1] + b1);
            float2 v1 = make_float2(acc[mi][ni][2] + b0, acc[mi][ni][3] + b1);
            *(float2*)&Cout[row0*N + col]       = v0;
            *(float2*)&Cout[(row0 + 8)*N + col] = v1;
        }
    }
}

// ----------------------------------------------------------------------------
// Attention v3 (known good): 2x2 pixel tile, 128 thr, warp = head.
// ----------------------------------------------------------------------------
#define KP 132
#define ATTN_SMEM ((64*KP*2 + 4*KP + 4*52) * 4)   // 70528 bytes

__global__ void __launch_bounds__(128) attn3_kernel(
    const float* __restrict__ qkv,
    const float* __restrict__ rpb,   // [NH][13][13]
    float* __restrict__ out)
{
    extern __shared__ float dsm[];
    float* sK = dsm;              // [64][KP]
    float* sV = sK + 64*KP;       // [64][KP]
    float* sq = sV + 64*KP;       // [4][KP]
    float* sc = sq + 4*KP;        // [4 heads][52]

    const int blk = blockIdx.x;          // 2048 = 2 * 32 * 32
    const int b  = blk >> 10;
    const int ti = (blk >> 5) & 31;
    const int tj = blk & 31;
    const int i0 = ti*2, j0 = tj*2;
    const int r0 = min(max(i0 - 3, 0), HH - 8);
    const int c0 = min(max(j0 - 3, 0), WW - 8);
    const int tid = threadIdx.x;
    const int h = tid >> 5;
    const int lane = tid & 31;

    #pragma unroll
    for (int it = 0; it < 32; it++) {
        int idx = tid + it*128;
        int row = idx >> 6, c4 = idx & 63;
        int wr = row >> 3, wc = row & 7;
        int tt = (b*HH + r0 + wr)*WW + c0 + wc;
        float4 v = ((const float4*)qkv)[tt*96 + 32 + c4];
        if (c4 < 32) *(float4*)&sK[row*KP + c4*4] = v;
        else         *(float4*)&sV[row*KP + (c4-32)*4] = v;
    }
    {
        int p = tid >> 5, c4 = tid & 31;
        int tt = (b*HH + i0 + (p >> 1))*WW + j0 + (p & 1);
        float4 v = ((const float4*)qkv)[tt*96 + c4];
        const float s = 0.17677669529663687f;   // 32^-0.5
        v.x *= s; v.y *= s; v.z *= s; v.w *= s;
        *(float4*)&sq[p*KP + c4*4] = v;
    }
    __syncthreads();

    const float* rp = rpb + h*169;

    #pragma unroll
    for (int p = 0; p < 4; p++) {
        const int i = i0 + (p >> 1), j = j0 + (p & 1);
        const int si = min(max(i - 3, 0), HH - KS);
        const int sj = min(max(j - 3, 0), WW - KS);
        const int wr0 = si - r0, wc0 = sj - c0;
        const int bi0 = 6 - (i - si), bj0 = 6 - (j - sj);

        float4 q[8];
        const float4* qp = (const float4*)(sq + p*KP + h*DH);
        #pragma unroll
        for (int u = 0; u < 8; u++) q[u] = qp[u];

        float s0, s1;
        {
            int n = lane;
            int np = n/7, nq = n - np*7;
            const float4* kp = (const float4*)(sK + ((wr0+np)*8 + wc0+nq)*KP + h*DH);
            float ax=0.f, ay=0.f, az=0.f, aw=0.f;
            #pragma unroll
            for (int u = 0; u < 8; u++) {
                float4 kv = kp[u];
                ax += q[u].x*kv.x; ay += q[u].y*kv.y;
                az += q[u].z*kv.z; aw += q[u].w*kv.w;
            }
            s0 = (ax+ay) + (az+aw) + rp[(np+bi0)*13 + nq+bj0];
        }
        const int n2 = lane + 32;
        if (n2 < KK) {
            int np = n2/7, nq = n2 - np*7;
            const float4* kp = (const float4*)(sK + ((wr0+np)*8 + wc0+nq)*KP + h*DH);
            float ax=0.f, ay=0.f, az=0.f, aw=0.f;
            #pragma unroll
            for (int u = 0; u < 8; u++) {
                float4 kv = kp[u];
                ax += q[u].x*kv.x; ay += q[u].y*kv.y;
                az += q[u].z*kv.z; aw += q[u].w*kv.w;
            }
            s1 = (ax+ay) + (az+aw) + rp[(np+bi0)*13 + nq+bj0];
        } else s1 = -1e30f;

        float m = fmaxf(s0, s1);
        #pragma unroll
        for (int o = 16; o > 0; o >>= 1) m = fmaxf(m, __shfl_xor_sync(0xffffffffu, m, o));
        float e0 = __expf(s0 - m);
        float e1 = (n2 < KK) ? __expf(s1 - m) : 0.f;
        float sum = e0 + e1;
        #pragma unroll
        for (int o = 16; o > 0; o >>= 1) sum += __shfl_xor_sync(0xffffffffu, sum, o);
        const float inv = 1.f / sum;

        __syncwarp();
        sc[h*52 + lane] = e0 * inv;
        if (n2 < KK) sc[h*52 + n2] = e1 * inv;
        __syncwarp();

        float oa = 0.f, ob = 0.f;
        #pragma unroll
        for (int np = 0; np < 7; np++) {
            const float* vrow = sV + ((wr0+np)*8 + wc0)*KP + h*DH + lane;
            const float* prow = sc + h*52 + np*7;
            oa += prow[0]*vrow[0*KP] + prow[2]*vrow[2*KP]
                + prow[4]*vrow[4*KP] + prow[6]*vrow[6*KP];
            ob += prow[1]*vrow[1*KP] + prow[3]*vrow[3*KP]
                + prow[5]*vrow[5*KP];
        }
        int tt = (b*HH + i)*WW + j;
        out[(size_t)tt*CC + h*DH + lane] = oa + ob;
        __syncwarp();
    }
}

// ----------------------------------------------------------------------------
// Final LayerNorm over C + NHWC -> NCHW transpose.
// ----------------------------------------------------------------------------
__global__ void ln_kernel(const float* __restrict__ y,
                          const float* __restrict__ g,
                          const float* __restrict__ bta,
                          float* __restrict__ out)
{
    __shared__ float s[64][133];
    __shared__ float mu[64], rs[64];

    const int row = blockIdx.x;
    const int b = row >> 6, i = row & 63;
    const int base = row * 64 * CC;
    const int tid = threadIdx.x;

    for (int idx = tid; idx < 64*CC; idx += 256) {
        int jj = idx >> 7, c = idx & 127;
        s[jj][c] = y[base + idx];
    }
    __syncthreads();

    if (tid < 64) {
        float sum = 0.f, sq = 0.f;
        #pragma unroll 8
        for (int c = 0; c < CC; c++) {
            float v = s[tid][c];
            sum += v; sq += v*v;
        }
        float m = sum * (1.f/CC);
        mu[tid] = m;
        rs[tid] = rsqrtf(sq * (1.f/CC) - m*m + 1e-5f);
    }
    __syncthreads();

    for (int idx = tid; idx < 64*CC; idx += 256) {
        int c = idx >> 6, jj = idx & 63;
        float v = (s[jj][c] - mu[jj]) * rs[jj] * g[c] + bta[c];
        out[((b*CC + c)*HH + i)*WW + jj] = v;
    }
}

// ----------------------------------------------------------------------------
extern "C" void kernel_launch(void* const* d_in, const int* in_sizes, int n_in,
                              void* d_out, int out_size)
{
    const float* x      = (const float*)d_in[0];
    const float* qkv_w  = (const float*)d_in[1];
    const float* qkv_b  = (const float*)d_in[2];
    const float* rpb    = (const float*)d_in[3];
    const float* proj_w = (const float*)d_in[4];
    const float* proj_b = (const float*)d_in[5];
    const float* ln_g   = (const float*)d_in[6];
    const float* ln_b   = (const float*)d_in[7];
    float* outp = (float*)d_out;

    float *qkvbuf, *attbuf, *y1, *y2;
    cudaGetSymbolAddress((void**)&qkvbuf, g_qkv);
    cudaGetSymbolAddress((void**)&attbuf, g_att);
    cudaGetSymbolAddress((void**)&y1, g_y1);
    cudaGetSymbolAddress((void**)&y2, g_y2);

    static int smem_set = 0;
    if (!smem_set) {
        cudaFuncSetAttribute(attn3_kernel,
                             cudaFuncAttributeMaxDynamicSharedMemorySize,
                             ATTN_SMEM);
        cudaFuncSetAttribute(sgemm_tc2_kernel,
                             cudaFuncAttributeMaxDynamicSharedMemorySize,
                             GEMM_SMEM);
        smem_set = 1;
    }

    dim3 gq(NTOK/64, (3*CC)/64);   // 128 x 6
    dim3 gp(NTOK/64, CC/64);       // 128 x 2
    const int RPB_L = NH*13*13;
    const int NATB = BB*32*32;     // 2048

    // ---- layer 0 ----
    sgemm_tc2_kernel<<<gq, 256, GEMM_SMEM>>>(x, 1, qkv_w, qkv_b, qkvbuf, 3*CC);
    attn3_kernel<<<NATB, 128, ATTN_SMEM>>>(qkvbuf, rpb, attbuf);
    sgemm_tc2_kernel<<<gp, 256, GEMM_SMEM>>>(attbuf, 0, proj_w, proj_b, y1, CC);

    // ---- layer 1 ----
    sgemm_tc2_kernel<<<gq, 256, GEMM_SMEM>>>(y1, 0, qkv_w + 3*CC*CC, qkv_b + 3*CC, qkvbuf, 3*CC);
    attn3_kernel<<<NATB, 128, ATTN_SMEM>>>(qkvbuf, rpb + RPB_L, attbuf);
    sgemm_tc2_kernel<<<gp, 256, GEMM_SMEM>>>(attbuf, 0, proj_w + CC*CC, proj_b + CC, y2, CC);

    // ---- LN + transpose ----
    ln_kernel<<<BB*HH, 256>>>(y2, ln_g, ln_b, outp);
}

// round 9
// speedup vs baseline: 1.0773x; 1.0773x over previous
#include <cuda_runtime.h>
#include <math.h>

#define HH 64
#define WW 64
#define BB 2
#define CC 128
#define NH 4
#define DH 32
#define KS 7
#define KK 49
#define NTOK (BB*HH*WW)   // 8192
#define QKV_STRIDE (3*CC) // 384

// scratch (device globals: no allocation allowed)
__device__ float g_qkv[NTOK * 3 * CC];
__device__ float g_att[NTOK * CC];
__device__ float g_y1 [NTOK * CC];
__device__ float g_y2 [NTOK * CC];

// ----------------------------------------------------------------------------
// tf32 helpers
// ----------------------------------------------------------------------------
__device__ __forceinline__ unsigned f2tf32(float f) {
    unsigned u;
    asm("cvt.rna.tf32.f32 %0, %1;" : "=r"(u) : "f"(f));
    return u;
}
__device__ __forceinline__ void split_tf32(float f, unsigned& hi, unsigned& lo) {
    hi = f2tf32(f);
    lo = f2tf32(f - __uint_as_float(hi));
}
__device__ __forceinline__ void mma8(float* c, const unsigned* a, const unsigned* b) {
    asm volatile(
        "mma.sync.aligned.m16n8k8.row.col.f32.tf32.tf32.f32 "
        "{%0,%1,%2,%3}, {%4,%5,%6,%7}, {%8,%9}, {%0,%1,%2,%3};"
        : "+f"(c[0]), "+f"(c[1]), "+f"(c[2]), "+f"(c[3])
        : "r"(a[0]), "r"(a[1]), "r"(a[2]), "r"(a[3]),
          "r"(b[0]), "r"(b[1]));
}

// ----------------------------------------------------------------------------
// Tensor-core SGEMM (3xTF32, split at staging) — unchanged from R8 (24 us).
// ----------------------------------------------------------------------------
#define SPK 68
#define GEMM_SMEM (4*64*SPK*4)   // 69632 bytes

__global__ void __launch_bounds__(256) sgemm_tc2_kernel(
    const float* __restrict__ A, int a_nchw,
    const float* __restrict__ W,
    const float* __restrict__ bias,
    float* __restrict__ Cout, int N)
{
    extern __shared__ unsigned usm[];
    unsigned* Ah = usm;
    unsigned* Al = Ah + 64*SPK;
    unsigned* Bh = Al + 64*SPK;
    unsigned* Bl = Bh + 64*SPK;

    const int bm = blockIdx.x * 64;
    const int bn = blockIdx.y * 64;
    const int tid  = threadIdx.x;
    const int w    = tid >> 5;
    const int lane = tid & 31;
    const int wm = w >> 2;
    const int wn = w & 3;
    const int g  = lane >> 2;
    const int t4 = lane & 3;

    float acc[2][2][4];
    #pragma unroll
    for (int mi = 0; mi < 2; mi++)
        #pragma unroll
        for (int ni = 0; ni < 2; ni++)
            #pragma unroll
            for (int u = 0; u < 4; u++) acc[mi][ni][u] = 0.f;

    #pragma unroll
    for (int kt = 0; kt < 2; kt++) {
        if (kt) __syncthreads();
        if (a_nchw) {
            const int b = bm >> 12;
            const int sp0 = bm & 4095;
            #pragma unroll
            for (int r = 0; r < 4; r++) {
                int idx = tid + r*256;
                int k = idx >> 4, m4 = idx & 15;
                float4 v = *(const float4*)&A[(b*CC + kt*64 + k)*4096 + sp0 + m4*4];
                unsigned h0,l0,h1,l1,h2,l2,h3,l3;
                split_tf32(v.x, h0, l0); split_tf32(v.y, h1, l1);
                split_tf32(v.z, h2, l2); split_tf32(v.w, h3, l3);
                Ah[(m4*4+0)*SPK + k] = h0; Al[(m4*4+0)*SPK + k] = l0;
                Ah[(m4*4+1)*SPK + k] = h1; Al[(m4*4+1)*SPK + k] = l1;
                Ah[(m4*4+2)*SPK + k] = h2; Al[(m4*4+2)*SPK + k] = l2;
                Ah[(m4*4+3)*SPK + k] = h3; Al[(m4*4+3)*SPK + k] = l3;
            }
        } else {
            #pragma unroll
            for (int r = 0; r < 4; r++) {
                int idx = tid + r*256;
                int m = idx >> 4, k4 = idx & 15;
                float4 v = ((const float4*)A)[(bm + m)*32 + kt*16 + k4];
                uint4 hv, lv;
                split_tf32(v.x, hv.x, lv.x); split_tf32(v.y, hv.y, lv.y);
                split_tf32(v.z, hv.z, lv.z); split_tf32(v.w, hv.w, lv.w);
                *(uint4*)&Ah[m*SPK + k4*4] = hv;
                *(uint4*)&Al[m*SPK + k4*4] = lv;
            }
        }
        #pragma unroll
        for (int r = 0; r < 4; r++) {
            int idx = tid + r*256;
            int n = idx >> 4, k4 = idx & 15;
            float4 v = ((const float4*)W)[(bn + n)*32 + kt*16 + k4];
            uint4 hv, lv;
            split_tf32(v.x, hv.x, lv.x); split_tf32(v.y, hv.y, lv.y);
            split_tf32(v.z, hv.z, lv.z); split_tf32(v.w, hv.w, lv.w);
            *(uint4*)&Bh[n*SPK + k4*4] = hv;
            *(uint4*)&Bl[n*SPK + k4*4] = lv;
        }
        __syncthreads();

        #pragma unroll
        for (int ks = 0; ks < 8; ks++) {
            const int k0 = ks*8;
            unsigned ah[2][4], al[2][4];
            #pragma unroll
            for (int mi = 0; mi < 2; mi++) {
                const int r0 = (wm*32 + mi*16 + g)*SPK + k0 + t4;
                const int r8 = r0 + 8*SPK;
                ah[mi][0] = Ah[r0];     ah[mi][1] = Ah[r8];
                ah[mi][2] = Ah[r0 + 4]; ah[mi][3] = Ah[r8 + 4];
                al[mi][0] = Al[r0];     al[mi][1] = Al[r8];
                al[mi][2] = Al[r0 + 4]; al[mi][3] = Al[r8 + 4];
            }
            unsigned bh[2][2], bl[2][2];
            #pragma unroll
            for (int ni = 0; ni < 2; ni++) {
                const int r0 = (wn*16 + ni*8 + g)*SPK + k0 + t4;
                bh[ni][0] = Bh[r0]; bh[ni][1] = Bh[r0 + 4];
                bl[ni][0] = Bl[r0]; bl[ni][1] = Bl[r0 + 4];
            }
            #pragma unroll
            for (int mi = 0; mi < 2; mi++)
                #pragma unroll
                for (int ni = 0; ni < 2; ni++) {
                    mma8(acc[mi][ni], ah[mi], bh[ni]);
                    mma8(acc[mi][ni], ah[mi], bl[ni]);
                    mma8(acc[mi][ni], al[mi], bh[ni]);
                }
        }
    }

    #pragma unroll
    for (int mi = 0; mi < 2; mi++) {
        #pragma unroll
        for (int ni = 0; ni < 2; ni++) {
            const int row0 = bm + wm*32 + mi*16 + g;
            const int col  = bn + wn*16 + ni*8 + t4*2;
            float b0 = bias[col], b1 = bias[col + 1];
            float2 v0 = make_float2(acc[mi][ni][0] + b0, acc[mi][ni][1] + b1);
            float2 v1 = make_float2(acc[mi][ni][2] + b0, acc[mi][ni][3] + b1);
            *(float2*)&Cout[row0*N + col]       = v0;
            *(float2*)&Cout[(row0 + 8)*N + col] = v1;
        }
    }
}

// ----------------------------------------------------------------------------
// Attention v6: 2x2 pixel tile, 256 threads, 8 warps = (head, pixel-pair).
// Each warp handles 2 pixels -> per-warp serial chain halved vs attn3;
// warps/SM 12 -> 24 at the same 3 blocks/SM.
// ----------------------------------------------------------------------------
#define KP 132
#define SCP 52
#define ATTN_SMEM ((64*KP*2 + 4*KP + 16*SCP) * 4)   // 73024 bytes

__global__ void __launch_bounds__(256) attn6_kernel(
    const float* __restrict__ qkv,
    const float* __restrict__ rpb,   // [NH][13][13]
    float* __restrict__ out)
{
    extern __shared__ float dsm[];
    float* sK = dsm;              // [64][KP]
    float* sV = sK + 64*KP;       // [64][KP]
    float* sq = sV + 64*KP;       // [4][KP]
    float* sc = sq + 4*KP;        // [16][SCP] probs, row = h*4+p

    const int blk = blockIdx.x;          // 2048 = 2 * 32 * 32
    const int b  = blk >> 10;
    const int ti = (blk >> 5) & 31;
    const int tj = blk & 31;
    const int i0 = ti*2, j0 = tj*2;
    const int r0 = min(max(i0 - 3, 0), HH - 8);
    const int c0 = min(max(j0 - 3, 0), WW - 8);
    const int tid = threadIdx.x;
    const int w = tid >> 5;
    const int lane = tid & 31;
    const int h = w & 3;            // head
    const int half = w >> 2;        // pixel pair 0/1

    // ---- stage K,V (8x8 window): 4096 float4 over 256 threads ----
    #pragma unroll
    for (int it = 0; it < 16; it++) {
        int idx = tid + it*256;
        int row = idx >> 6, c4 = idx & 63;
        int wr = row >> 3, wc = row & 7;
        int tt = (b*HH + r0 + wr)*WW + c0 + wc;
        float4 v = ((const float4*)qkv)[tt*96 + 32 + c4];
        if (c4 < 32) *(float4*)&sK[row*KP + c4*4] = v;
        else         *(float4*)&sV[row*KP + (c4-32)*4] = v;
    }
    // ---- stage 4 scaled q rows (first 128 threads) ----
    if (tid < 128) {
        int p = tid >> 5, c4 = tid & 31;
        int tt = (b*HH + i0 + (p >> 1))*WW + j0 + (p & 1);
        float4 v = ((const float4*)qkv)[tt*96 + c4];
        const float s = 0.17677669529663687f;   // 32^-0.5
        v.x *= s; v.y *= s; v.z *= s; v.w *= s;
        *(float4*)&sq[p*KP + c4*4] = v;
    }
    __syncthreads();

    const float* rp = rpb + h*169;

    #pragma unroll
    for (int pp = 0; pp < 2; pp++) {
        const int p = half*2 + pp;
        const int i = i0 + (p >> 1), j = j0 + (p & 1);
        const int si = min(max(i - 3, 0), HH - KS);
        const int sj = min(max(j - 3, 0), WW - KS);
        const int wr0 = si - r0, wc0 = sj - c0;
        const int bi0 = 6 - (i - si), bj0 = 6 - (j - sj);

        float4 q[8];
        const float4* qp = (const float4*)(sq + p*KP + h*DH);
        #pragma unroll
        for (int u = 0; u < 8; u++) q[u] = qp[u];

        float s0, s1;
        {
            int n = lane;
            int np = n/7, nq = n - np*7;
            const float4* kp = (const float4*)(sK + ((wr0+np)*8 + wc0+nq)*KP + h*DH);
            float ax=0.f, ay=0.f, az=0.f, aw=0.f;
            #pragma unroll
            for (int u = 0; u < 8; u++) {
                float4 kv = kp[u];
                ax += q[u].x*kv.x; ay += q[u].y*kv.y;
                az += q[u].z*kv.z; aw += q[u].w*kv.w;
            }
            s0 = (ax+ay) + (az+aw) + rp[(np+bi0)*13 + nq+bj0];
        }
        const int n2 = lane + 32;
        if (n2 < KK) {
            int np = n2/7, nq = n2 - np*7;
            const float4* kp = (const float4*)(sK + ((wr0+np)*8 + wc0+nq)*KP + h*DH);
            float ax=0.f, ay=0.f, az=0.f, aw=0.f;
            #pragma unroll
            for (int u = 0; u < 8; u++) {
                float4 kv = kp[u];
                ax += q[u].x*kv.x; ay += q[u].y*kv.y;
                az += q[u].z*kv.z; aw += q[u].w*kv.w;
            }
            s1 = (ax+ay) + (az+aw) + rp[(np+bi0)*13 + nq+bj0];
        } else s1 = -1e30f;

        // ---- softmax (warp-resident) ----
        float m = fmaxf(s0, s1);
        #pragma unroll
        for (int o = 16; o > 0; o >>= 1) m = fmaxf(m, __shfl_xor_sync(0xffffffffu, m, o));
        float e0 = __expf(s0 - m);
        float e1 = (n2 < KK) ? __expf(s1 - m) : 0.f;
        float sum = e0 + e1;
        #pragma unroll
        for (int o = 16; o > 0; o >>= 1) sum += __shfl_xor_sync(0xffffffffu, sum, o);
        const float inv = 1.f / sum;

        float* scrow = sc + (h*4 + p)*SCP;
        __syncwarp();
        scrow[lane] = e0 * inv;
        if (n2 < KK) scrow[n2] = e1 * inv;
        __syncwarp();

        // ---- AV: lane = d, probs via smem broadcast ----
        float oa = 0.f, ob = 0.f;
        #pragma unroll
        for (int np = 0; np < 7; np++) {
            const float* vrow = sV + ((wr0+np)*8 + wc0)*KP + h*DH + lane;
            const float* prow = scrow + np*7;
            oa += prow[0]*vrow[0*KP] + prow[2]*vrow[2*KP]
                + prow[4]*vrow[4*KP] + prow[6]*vrow[6*KP];
            ob += prow[1]*vrow[1*KP] + prow[3]*vrow[3*KP]
                + prow[5]*vrow[5*KP];
        }
        int tt = (b*HH + i)*WW + j;
        out[(size_t)tt*CC + h*DH + lane] = oa + ob;
        __syncwarp();
    }
}

// ----------------------------------------------------------------------------
// Final LayerNorm over C + NHWC -> NCHW transpose.
// ----------------------------------------------------------------------------
__global__ void ln_kernel(const float* __restrict__ y,
                          const float* __restrict__ g,
                          const float* __restrict__ bta,
                          float* __restrict__ out)
{
    __shared__ float s[64][133];
    __shared__ float mu[64], rs[64];

    const int row = blockIdx.x;
    const int b = row >> 6, i = row & 63;
    const int base = row * 64 * CC;
    const int tid = threadIdx.x;

    for (int idx = tid; idx < 64*CC; idx += 256) {
        int jj = idx >> 7, c = idx & 127;
        s[jj][c] = y[base + idx];
    }
    __syncthreads();

    if (tid < 64) {
        float sum = 0.f, sq = 0.f;
        #pragma unroll 8
        for (int c = 0; c < CC; c++) {
            float v = s[tid][c];
            sum += v; sq += v*v;
        }
        float m = sum * (1.f/CC);
        mu[tid] = m;
        rs[tid] = rsqrtf(sq * (1.f/CC) - m*m + 1e-5f);
    }
    __syncthreads();

    for (int idx = tid; idx < 64*CC; idx += 256) {
        int c = idx >> 6, jj = idx & 63;
        float v = (s[jj][c] - mu[jj]) * rs[jj] * g[c] + bta[c];
        out[((b*CC + c)*HH + i)*WW + jj] = v;
    }
}

// ----------------------------------------------------------------------------
extern "C" void kernel_launch(void* const* d_in, const int* in_sizes, int n_in,
                              void* d_out, int out_size)
{
    const float* x      = (const float*)d_in[0];
    const float* qkv_w  = (const float*)d_in[1];
    const float* qkv_b  = (const float*)d_in[2];
    const float* rpb    = (const float*)d_in[3];
    const float* proj_w = (const float*)d_in[4];
    const float* proj_b = (const float*)d_in[5];
    const float* ln_g   = (const float*)d_in[6];
    const float* ln_b   = (const float*)d_in[7];
    float* outp = (float*)d_out;

    float *qkvbuf, *attbuf, *y1, *y2;
    cudaGetSymbolAddress((void**)&qkvbuf, g_qkv);
    cudaGetSymbolAddress((void**)&attbuf, g_att);
    cudaGetSymbolAddress((void**)&y1, g_y1);
    cudaGetSymbolAddress((void**)&y2, g_y2);

    static int smem_set = 0;
    if (!smem_set) {
        cudaFuncSetAttribute(attn6_kernel,
                             cudaFuncAttributeMaxDynamicSharedMemorySize,
                             ATTN_SMEM);
        cudaFuncSetAttribute(sgemm_tc2_kernel,
                             cudaFuncAttributeMaxDynamicSharedMemorySize,
                             GEMM_SMEM);
        smem_set = 1;
    }

    dim3 gq(NTOK/64, (3*CC)/64);   // 128 x 6
    dim3 gp(NTOK/64, CC/64);       // 128 x 2
    const int RPB_L = NH*13*13;
    const int NATB = BB*32*32;     // 2048

    // ---- layer 0 ----
    sgemm_tc2_kernel<<<gq, 256, GEMM_SMEM>>>(x, 1, qkv_w, qkv_b, qkvbuf, 3*CC);
    attn6_kernel<<<NATB, 256, ATTN_SMEM>>>(qkvbuf, rpb, attbuf);
    sgemm_tc2_kernel<<<gp, 256, GEMM_SMEM>>>(attbuf, 0, proj_w, proj_b, y1, CC);

    // ---- layer 1 ----
    sgemm_tc2_kernel<<<gq, 256, GEMM_SMEM>>>(y1, 0, qkv_w + 3*CC*CC, qkv_b + 3*CC, qkvbuf, 3*CC);
    attn6_kernel<<<NATB, 256, ATTN_SMEM>>>(qkvbuf, rpb + RPB_L, attbuf);
    sgemm_tc2_kernel<<<gp, 256, GEMM_SMEM>>>(attbuf, 0, proj_w + CC*CC, proj_b + CC, y2, CC);

    // ---- LN + transpose ----
    ln_kernel<<<BB*HH, 256>>>(y2, ln_g, ln_b, outp);
}

// round 10
// speedup vs baseline: 1.0794x; 1.0019x over previous
#include <cuda_runtime.h>
#include <math.h>

#define HH 64
#define WW 64
#define BB 2
#define CC 128
#define NH 4
#define DH 32
#define KS 7
#define KK 49
#define NTOK (BB*HH*WW)   // 8192
#define QKV_STRIDE (3*CC) // 384

// scratch (device globals: no allocation allowed)
__device__ float g_qkv[NTOK * 3 * CC];
__device__ float g_att[NTOK * CC];
__device__ float g_y1 [NTOK * CC];
__device__ float g_y2 [NTOK * CC];

// ----------------------------------------------------------------------------
// tf32 helpers
// ----------------------------------------------------------------------------
__device__ __forceinline__ unsigned f2tf32(float f) {
    unsigned u;
    asm("cvt.rna.tf32.f32 %0, %1;" : "=r"(u) : "f"(f));
    return u;
}
__device__ __forceinline__ void split_tf32(float f, unsigned& hi, unsigned& lo) {
    hi = f2tf32(f);
    lo = f2tf32(f - __uint_as_float(hi));
}
__device__ __forceinline__ void mma8(float* c, const unsigned* a, const unsigned* b) {
    asm volatile(
        "mma.sync.aligned.m16n8k8.row.col.f32.tf32.tf32.f32 "
        "{%0,%1,%2,%3}, {%4,%5,%6,%7}, {%8,%9}, {%0,%1,%2,%3};"
        : "+f"(c[0]), "+f"(c[1]), "+f"(c[2]), "+f"(c[3])
        : "r"(a[0]), "r"(a[1]), "r"(a[2]), "r"(a[3]),
          "r"(b[0]), "r"(b[1]));
}

// ----------------------------------------------------------------------------
// Tensor-core SGEMM (3xTF32, split at staging) — unchanged from R8 (24 us).
// ----------------------------------------------------------------------------
#define SPK 68
#define GEMM_SMEM (4*64*SPK*4)   // 69632 bytes

__global__ void __launch_bounds__(256) sgemm_tc2_kernel(
    const float* __restrict__ A, int a_nchw,
    const float* __restrict__ W,
    const float* __restrict__ bias,
    float* __restrict__ Cout, int N)
{
    extern __shared__ unsigned usm[];
    unsigned* Ah = usm;
    unsigned* Al = Ah + 64*SPK;
    unsigned* Bh = Al + 64*SPK;
    unsigned* Bl = Bh + 64*SPK;

    const int bm = blockIdx.x * 64;
    const int bn = blockIdx.y * 64;
    const int tid  = threadIdx.x;
    const int w    = tid >> 5;
    const int lane = tid & 31;
    const int wm = w >> 2;
    const int wn = w & 3;
    const int g  = lane >> 2;
    const int t4 = lane & 3;

    float acc[2][2][4];
    #pragma unroll
    for (int mi = 0; mi < 2; mi++)
        #pragma unroll
        for (int ni = 0; ni < 2; ni++)
            #pragma unroll
            for (int u = 0; u < 4; u++) acc[mi][ni][u] = 0.f;

    #pragma unroll
    for (int kt = 0; kt < 2; kt++) {
        if (kt) __syncthreads();
        if (a_nchw) {
            const int b = bm >> 12;
            const int sp0 = bm & 4095;
            #pragma unroll
            for (int r = 0; r < 4; r++) {
                int idx = tid + r*256;
                int k = idx >> 4, m4 = idx & 15;
                float4 v = *(const float4*)&A[(b*CC + kt*64 + k)*4096 + sp0 + m4*4];
                unsigned h0,l0,h1,l1,h2,l2,h3,l3;
                split_tf32(v.x, h0, l0); split_tf32(v.y, h1, l1);
                split_tf32(v.z, h2, l2); split_tf32(v.w, h3, l3);
                Ah[(m4*4+0)*SPK + k] = h0; Al[(m4*4+0)*SPK + k] = l0;
                Ah[(m4*4+1)*SPK + k] = h1; Al[(m4*4+1)*SPK + k] = l1;
                Ah[(m4*4+2)*SPK + k] = h2; Al[(m4*4+2)*SPK + k] = l2;
                Ah[(m4*4+3)*SPK + k] = h3; Al[(m4*4+3)*SPK + k] = l3;
            }
        } else {
            #pragma unroll
            for (int r = 0; r < 4; r++) {
                int idx = tid + r*256;
                int m = idx >> 4, k4 = idx & 15;
                float4 v = ((const float4*)A)[(bm + m)*32 + kt*16 + k4];
                uint4 hv, lv;
                split_tf32(v.x, hv.x, lv.x); split_tf32(v.y, hv.y, lv.y);
                split_tf32(v.z, hv.z, lv.z); split_tf32(v.w, hv.w, lv.w);
                *(uint4*)&Ah[m*SPK + k4*4] = hv;
                *(uint4*)&Al[m*SPK + k4*4] = lv;
            }
        }
        #pragma unroll
        for (int r = 0; r < 4; r++) {
            int idx = tid + r*256;
            int n = idx >> 4, k4 = idx & 15;
            float4 v = ((const float4*)W)[(bn + n)*32 + kt*16 + k4];
            uint4 hv, lv;
            split_tf32(v.x, hv.x, lv.x); split_tf32(v.y, hv.y, lv.y);
            split_tf32(v.z, hv.z, lv.z); split_tf32(v.w, hv.w, lv.w);
            *(uint4*)&Bh[n*SPK + k4*4] = hv;
            *(uint4*)&Bl[n*SPK + k4*4] = lv;
        }
        __syncthreads();

        #pragma unroll
        for (int ks = 0; ks < 8; ks++) {
            const int k0 = ks*8;
            unsigned ah[2][4], al[2][4];
            #pragma unroll
            for (int mi = 0; mi < 2; mi++) {
                const int r0 = (wm*32 + mi*16 + g)*SPK + k0 + t4;
                const int r8 = r0 + 8*SPK;
                ah[mi][0] = Ah[r0];     ah[mi][1] = Ah[r8];
                ah[mi][2] = Ah[r0 + 4]; ah[mi][3] = Ah[r8 + 4];
                al[mi][0] = Al[r0];     al[mi][1] = Al[r8];
                al[mi][2] = Al[r0 + 4]; al[mi][3] = Al[r8 + 4];
            }
            unsigned bh[2][2], bl[2][2];
            #pragma unroll
            for (int ni = 0; ni < 2; ni++) {
                const int r0 = (wn*16 + ni*8 + g)*SPK + k0 + t4;
                bh[ni][0] = Bh[r0]; bh[ni][1] = Bh[r0 + 4];
                bl[ni][0] = Bl[r0]; bl[ni][1] = Bl[r0 + 4];
            }
            #pragma unroll
            for (int mi = 0; mi < 2; mi++)
                #pragma unroll
                for (int ni = 0; ni < 2; ni++) {
                    mma8(acc[mi][ni], ah[mi], bh[ni]);
                    mma8(acc[mi][ni], ah[mi], bl[ni]);
                    mma8(acc[mi][ni], al[mi], bh[ni]);
                }
        }
    }

    #pragma unroll
    for (int mi = 0; mi < 2; mi++) {
        #pragma unroll
        for (int ni = 0; ni < 2; ni++) {
            const int row0 = bm + wm*32 + mi*16 + g;
            const int col  = bn + wn*16 + ni*8 + t4*2;
            float b0 = bias[col], b1 = bias[col + 1];
            float2 v0 = make_float2(acc[mi][ni][0] + b0, acc[mi][ni][1] + b1);
            float2 v1 = make_float2(acc[mi][ni][2] + b0, acc[mi][ni][3] + b1);
            *(float2*)&Cout[row0*N + col]       = v0;
            *(float2*)&Cout[(row0 + 8)*N + col] = v1;
        }
    }
}

// ----------------------------------------------------------------------------
// Attention v7: 2x2 pixel tile, 256 threads.
// QK phase:  warp = (head, token-round); lane = window token; k-row loaded
//            ONCE into regs, reused across all 4 pixels (4x fewer k phases).
//            Split-softmax partials (m, sum, unnormalized e) to smem.
// AV phase:  warp = (head, pixel-half); merge the two softmax partials
//            analytically: o = s0*sum(rows<4) + s1*sum(rows>=4).
// ----------------------------------------------------------------------------
#define KP 132
#define SCP 68
#define MS_OFF (64*KP*2 + 4*KP + 16*SCP)          // float offset of ms[]
#define ATTN_SMEM ((MS_OFF + 64) * 4)             // + 32 float2 = 64 floats

__global__ void __launch_bounds__(256) attn7_kernel(
    const float* __restrict__ qkv,
    const float* __restrict__ rpb,   // [NH][13][13]
    float* __restrict__ out)
{
    extern __shared__ float dsm[];
    float*  sK = dsm;                 // [64][KP]
    float*  sV = sK + 64*KP;          // [64][KP]
    float*  sq = sV + 64*KP;          // [4][KP]
    float*  sc = sq + 4*KP;           // [16][SCP] unnormalized e, idx by wtok
    float2* ms = (float2*)(dsm + MS_OFF);  // [16][2] (m, sum) per (h*4+p, round)

    const int blk = blockIdx.x;          // 2048 = 2 * 32 * 32
    const int b  = blk >> 10;
    const int ti = (blk >> 5) & 31;
    const int tj = blk & 31;
    const int i0 = ti*2, j0 = tj*2;
    const int r0 = min(max(i0 - 3, 0), HH - 8);
    const int c0 = min(max(j0 - 3, 0), WW - 8);
    const int tid = threadIdx.x;
    const int w = tid >> 5;
    const int lane = tid & 31;
    const int h = w & 3;            // head
    const int rnd = w >> 2;         // token round (QK) / pixel half (AV)

    // ---- stage K,V (8x8 window): 4096 float4 over 256 threads ----
    #pragma unroll
    for (int it = 0; it < 16; it++) {
        int idx = tid + it*256;
        int row = idx >> 6, c4 = idx & 63;
        int wr = row >> 3, wc = row & 7;
        int tt = (b*HH + r0 + wr)*WW + c0 + wc;
        float4 v = ((const float4*)qkv)[tt*96 + 32 + c4];
        if (c4 < 32) *(float4*)&sK[row*KP + c4*4] = v;
        else         *(float4*)&sV[row*KP + (c4-32)*4] = v;
    }
    // ---- stage 4 scaled q rows (first 128 threads) ----
    if (tid < 128) {
        int p = tid >> 5, c4 = tid & 31;
        int tt = (b*HH + i0 + (p >> 1))*WW + j0 + (p & 1);
        float4 v = ((const float4*)qkv)[tt*96 + c4];
        const float s = 0.17677669529663687f;   // 32^-0.5
        v.x *= s; v.y *= s; v.z *= s; v.w *= s;
        *(float4*)&sq[p*KP + c4*4] = v;
    }
    __syncthreads();

    // per-pixel geometry (shared by both phases)
    int pwr0[4], pwc0[4], pbi0[4], pbj0[4];
    #pragma unroll
    for (int p = 0; p < 4; p++) {
        int i = i0 + (p >> 1), j = j0 + (p & 1);
        int si = min(max(i - 3, 0), HH - KS);
        int sj = min(max(j - 3, 0), WW - KS);
        pwr0[p] = si - r0;  pwc0[p] = sj - c0;
        pbi0[p] = 6 - (i - si);  pbj0[p] = 6 - (j - sj);
    }
    const float* rp = rpb + h*169;

    // ================= QK phase: warp = (h, rnd), lane = token =============
    {
        const int wtok = rnd*32 + lane;       // window token 0..63
        const int twr = wtok >> 3, twc = wtok & 7;
        float4 kreg[8];
        const float4* kp = (const float4*)(sK + wtok*KP + h*DH);
        #pragma unroll
        for (int u = 0; u < 8; u++) kreg[u] = kp[u];

        #pragma unroll
        for (int p = 0; p < 4; p++) {
            const int np = twr - pwr0[p];
            const int nq = twc - pwc0[p];
            const bool valid = (np >= 0) & (np < KS) & (nq >= 0) & (nq < KS);

            const float4* qp = (const float4*)(sq + p*KP + h*DH);
            float ax=0.f, ay=0.f, az=0.f, aw=0.f;
            #pragma unroll
            for (int u = 0; u < 8; u++) {
                float4 q2 = qp[u];   // broadcast LDS.128
                ax += q2.x*kreg[u].x; ay += q2.y*kreg[u].y;
                az += q2.z*kreg[u].z; aw += q2.w*kreg[u].w;
            }
            float s = (ax+ay) + (az+aw);
            if (valid) s += rp[(np + pbi0[p])*13 + nq + pbj0[p]];
            s = valid ? s : -1e30f;

            // warp-local softmax partial over this round's 32 tokens
            float m = s;
            #pragma unroll
            for (int o = 16; o > 0; o >>= 1)
                m = fmaxf(m, __shfl_xor_sync(0xffffffffu, m, o));
            float e = __expf(s - m);          // invalid -> exp(-huge) = 0
            float sum = e;
            #pragma unroll
            for (int o = 16; o > 0; o >>= 1)
                sum += __shfl_xor_sync(0xffffffffu, sum, o);

            sc[(h*4 + p)*SCP + wtok] = e;
            if (lane == 0) ms[(h*4 + p)*2 + rnd] = make_float2(m, sum);
        }
    }
    __syncthreads();

    // ================= AV phase: warp = (h, half), lane = d ================
    #pragma unroll
    for (int pp = 0; pp < 2; pp++) {
        const int p = rnd*2 + pp;
        const int wr0 = pwr0[p], wc0 = pwc0[p];

        float2 p0 = ms[(h*4 + p)*2 + 0];
        float2 p1 = ms[(h*4 + p)*2 + 1];
        float M  = fmaxf(p0.x, p1.x);
        float x0 = __expf(p0.x - M);
        float x1 = __expf(p1.x - M);
        float inv = 1.f / (p0.y*x0 + p1.y*x1);
        float s0 = x0*inv, s1 = x1*inv;

        const float* prow = sc + (h*4 + p)*SCP;
        float oa = 0.f, ob = 0.f;     // rows<4 (round 0) / rows>=4 (round 1)
        #pragma unroll
        for (int np = 0; np < 7; np++) {
            const int wrow = wr0 + np;
            const float* vbase = sV + (wrow*8 + wc0)*KP + h*DH + lane;
            const float* pb = prow + wrow*8 + wc0;
            float racc = pb[0]*vbase[0]
                       + pb[1]*vbase[1*KP]
                       + pb[2]*vbase[2*KP]
                       + pb[3]*vbase[3*KP]
                       + pb[4]*vbase[4*KP]
                       + pb[5]*vbase[5*KP]
                       + pb[6]*vbase[6*KP];
            if (wrow < 4) oa += racc; else ob += racc;
        }
        int i = i0 + (p >> 1), j = j0 + (p & 1);
        int tt = (b*HH + i)*WW + j;
        out[(size_t)tt*CC + h*DH + lane] = s0*oa + s1*ob;
    }
}

// ----------------------------------------------------------------------------
// Final LayerNorm over C + NHWC -> NCHW transpose.
// ----------------------------------------------------------------------------
__global__ void ln_kernel(const float* __restrict__ y,
                          const float* __restrict__ g,
                          const float* __restrict__ bta,
                          float* __restrict__ out)
{
    __shared__ float s[64][133];
    __shared__ float mu[64], rs[64];

    const int row = blockIdx.x;
    const int b = row >> 6, i = row & 63;
    const int base = row * 64 * CC;
    const int tid = threadIdx.x;

    for (int idx = tid; idx < 64*CC; idx += 256) {
        int jj = idx >> 7, c = idx & 127;
        s[jj][c] = y[base + idx];
    }
    __syncthreads();

    if (tid < 64) {
        float sum = 0.f, sq = 0.f;
        #pragma unroll 8
        for (int c = 0; c < CC; c++) {
            float v = s[tid][c];
            sum += v; sq += v*v;
        }
        float m = sum * (1.f/CC);
        mu[tid] = m;
        rs[tid] = rsqrtf(sq * (1.f/CC) - m*m + 1e-5f);
    }
    __syncthreads();

    for (int idx = tid; idx < 64*CC; idx += 256) {
        int c = idx >> 6, jj = idx & 63;
        float v = (s[jj][c] - mu[jj]) * rs[jj] * g[c] + bta[c];
        out[((b*CC + c)*HH + i)*WW + jj] = v;
    }
}

// ----------------------------------------------------------------------------
extern "C" void kernel_launch(void* const* d_in, const int* in_sizes, int n_in,
                              void* d_out, int out_size)
{
    const float* x      = (const float*)d_in[0];
    const float* qkv_w  = (const float*)d_in[1];
    const float* qkv_b  = (const float*)d_in[2];
    const float* rpb    = (const float*)d_in[3];
    const float* proj_w = (const float*)d_in[4];
    const float* proj_b = (const float*)d_in[5];
    const float* ln_g   = (const float*)d_in[6];
    const float* ln_b   = (const float*)d_in[7];
    float* outp = (float*)d_out;

    float *qkvbuf, *attbuf, *y1, *y2;
    cudaGetSymbolAddress((void**)&qkvbuf, g_qkv);
    cudaGetSymbolAddress((void**)&attbuf, g_att);
    cudaGetSymbolAddress((void**)&y1, g_y1);
    cudaGetSymbolAddress((void**)&y2, g_y2);

    static int smem_set = 0;
    if (!smem_set) {
        cudaFuncSetAttribute(attn7_kernel,
                             cudaFuncAttributeMaxDynamicSharedMemorySize,
                             ATTN_SMEM);
        cudaFuncSetAttribute(sgemm_tc2_kernel,
                             cudaFuncAttributeMaxDynamicSharedMemorySize,
                             GEMM_SMEM);
        smem_set = 1;
    }

    dim3 gq(NTOK/64, (3*CC)/64);   // 128 x 6
    dim3 gp(NTOK/64, CC/64);       // 128 x 2
    const int RPB_L = NH*13*13;
    const int NATB = BB*32*32;     // 2048

    // ---- layer 0 ----
    sgemm_tc2_kernel<<<gq, 256, GEMM_SMEM>>>(x, 1, qkv_w, qkv_b, qkvbuf, 3*CC);
    attn7_kernel<<<NATB, 256, ATTN_SMEM>>>(qkvbuf, rpb, attbuf);
    sgemm_tc2_kernel<<<gp, 256, GEMM_SMEM>>>(attbuf, 0, proj_w, proj_b, y1, CC);

    // ---- layer 1 ----
    sgemm_tc2_kernel<<<gq, 256, GEMM_SMEM>>>(y1, 0, qkv_w + 3*CC*CC, qkv_b + 3*CC, qkvbuf, 3*CC);
    attn7_kernel<<<NATB, 256, ATTN_SMEM>>>(qkvbuf, rpb + RPB_L, attbuf);
    sgemm_tc2_kernel<<<gp, 256, GEMM_SMEM>>>(attbuf, 0, proj_w + CC*CC, proj_b + CC, y2, CC);

    // ---- LN + transpose ----
    ln_kernel<<<BB*HH, 256>>>(y2, ln_g, ln_b, outp);
}